// round 15
// baseline (speedup 1.0000x reference)
#include <cuda_runtime.h>
#include <cuda_fp16.h>
#include <cstdint>

// Problem constants
#define Bsz   128
#define Himg  28
#define Wimg  28
#define C     512
#define WS    7
#define NH    16
#define HD    32
#define NWIN  16
#define L     49
#define NTOK  (Bsz*Himg*Wimg)        // 100352
#define NWH   (Bsz*NWIN*NH)          // 32768
#define QSCALE 0.17677669529663687f

// ---------------- scratch (device globals; packed half2 words) -------------
__device__ uint32_t g_q [Bsz*NWIN*NH*L*HD/2];   // [wh][l][d/2]
__device__ uint32_t g_k [Bsz*NWIN*NH*L*HD/2];
__device__ uint32_t g_v [Bsz*NWIN*NH*L*HD/2];
__device__ uint32_t g_ao[(size_t)NTOK*C/2];     // attn out halves [tok][256]
__device__ uint32_t g_x16[(size_t)NTOK*C/2];    // x halves [tok][256]
__device__ uint32_t g_wqkvT16[1536*256];        // w_qkv^T halves [n][k/2]
__device__ uint32_t g_wprojT16[512*256];        // w_proj^T halves [n][k/2]
__device__ float    g_bm[256*64*56];            // bias+mask [winImg*16+head][64][56]

__device__ __forceinline__ uint32_t pack2(float a, float b) {
    __half2 h = __floats2half2_rn(a, b);
    return *(uint32_t*)&h;
}
__device__ __forceinline__ uint32_t smem_u32(const void* p) {
    uint32_t a;
    asm("{ .reg .u64 t; cvta.to.shared.u64 t, %1; cvt.u32.u64 %0, t; }" : "=r"(a) : "l"(p));
    return a;
}
__device__ __forceinline__ void cp_async16(uint32_t dst, const void* src) {
    asm volatile("cp.async.cg.shared.global [%0], [%1], 16;" :: "r"(dst), "l"(src) : "memory");
}
#define CP_COMMIT()  asm volatile("cp.async.commit_group;" ::: "memory")
#define CP_WAIT(n)   asm volatile("cp.async.wait_group %0;" :: "n"(n) : "memory")

// ldmatrix x4 (sm_75+, arch-agnostic)
__device__ __forceinline__ void ldsm4(uint32_t& r0, uint32_t& r1, uint32_t& r2,
                                      uint32_t& r3, uint32_t addr) {
    asm volatile("ldmatrix.sync.aligned.m8n8.x4.shared.b16 {%0,%1,%2,%3}, [%4];"
                 : "=r"(r0), "=r"(r1), "=r"(r2), "=r"(r3) : "r"(addr));
}

// m16n8k16 f16 mma, fp32 accumulate
__device__ __forceinline__ void mma_f16(float* c, const uint32_t* a, const uint32_t* b) {
    asm volatile(
        "mma.sync.aligned.m16n8k16.row.col.f32.f16.f16.f32 "
        "{%0,%1,%2,%3}, {%4,%5,%6,%7}, {%8,%9}, {%0,%1,%2,%3};\n"
        : "+f"(c[0]), "+f"(c[1]), "+f"(c[2]), "+f"(c[3])
        : "r"(a[0]), "r"(a[1]), "r"(a[2]), "r"(a[3]), "r"(b[0]), "r"(b[1]));
}

// ======================= x -> half2 convert (one-shot) =====================
__global__ __launch_bounds__(256) void cvt_x_kernel(const float* __restrict__ x)
{
    size_t i = (size_t)blockIdx.x * 256 + threadIdx.x;   // float4 index
    float4 v = *(const float4*)(x + i * 4);
    uint2 w;
    w.x = pack2(v.x, v.y);
    w.y = pack2(v.z, v.w);
    *(uint2*)(g_x16 + i * 2) = w;
}

// ======================= weight transpose + cvt (tiny) =====================
__global__ void wT16_kernel(const float* __restrict__ src, int NC, int mode)
{
    uint32_t* dst = mode ? g_wprojT16 : g_wqkvT16;
    int n  = blockIdx.x;
    int kw = threadIdx.x;     // 0..255
    float a = src[(size_t)(2 * kw) * NC + n];
    float b = src[(size_t)(2 * kw + 1) * NC + n];
    dst[(size_t)n * 256 + kw] = pack2(a, b);
}

// ======================= bias+mask precompute (tiny, once) =================
__global__ void bm_precompute_kernel(const float* __restrict__ mask,
                                     const float* __restrict__ bias_table,
                                     const int*   __restrict__ rel_index)
{
    const int pair = blockIdx.x;            // winImg*16 + head
    const int winImg = pair >> 4, head = pair & 15;
    float* dst = g_bm + (size_t)pair * 64 * 56;
    for (int i = threadIdx.x; i < 64 * 56; i += blockDim.x) {
        int r = i / 56, col = i - r * 56;
        float v;
        if (r < 49)
            v = (col < 49)
                ? bias_table[rel_index[r * 49 + col] * NH + head] + mask[winImg * (L*L) + r * 49 + col]
                : -1e30f;
        else
            v = 0.f;
        dst[i] = v;
    }
}

// ======================= fp16 mma GEMM, 3-stage cp.async + ldmatrix ========
// Single __syncthreads per chunk: loads for ch+2 are issued AFTER compute(ch),
// targeting buffer (ch+2)%3 == (ch-1)%3 whose readers all passed this
// iteration's barrier. Cover for chunk ch's loads >= 1 full chunk compute.
#define SPAD   36
#define CHUNKW (128*SPAD)
#define NCH    8                     // 512 halves / 64

__global__ __launch_bounds__(256) void gemm_mma_kernel(
    const float* __restrict__ bias, float* __restrict__ outp, int mode)
{
    extern __shared__ uint32_t dsm[];
    uint32_t* Asb = dsm;                 // [3][128][SPAD]
    uint32_t* Bsb = dsm + 3 * CHUNKW;    // [3][128][SPAD]

    const int tid  = threadIdx.x;
    const int wid  = tid >> 5, lane = tid & 31;
    const int warp_m = wid & 1;
    const int warp_n = wid >> 1;
    const int bm = blockIdx.y * 128;
    const int bn = blockIdx.x * 128;
    const int grp = lane >> 2, thr = lane & 3;
    const int quad = lane >> 3, lrw = lane & 7;   // ldmatrix lane mapping

    const uint32_t* A  = (mode == 0) ? g_x16 : g_ao;
    const uint32_t* BT = (mode == 0) ? g_wqkvT16 : g_wprojT16;

    const int lrow = tid >> 3;            // staging row 0..31
    const int lc4  = (tid & 7) << 2;      // staging word 0..28

    // per-lane ldmatrix base addresses
    const uint32_t smb = smem_u32(dsm);
    const uint32_t aAddr0 = smb +
        (((warp_m * 64 + (quad & 1) * 8 + lrw) * SPAD + (quad >> 1) * 4) << 2);
    const uint32_t bAddr0 = smb + ((3 * CHUNKW) << 2) +
        (((warp_n * 32 + (quad >> 1) * 8 + lrw) * SPAD + (quad & 1) * 4) << 2);

    float c[4][4][4];
    #pragma unroll
    for (int mt = 0; mt < 4; mt++)
        #pragma unroll
        for (int nt = 0; nt < 4; nt++)
            #pragma unroll
            for (int e = 0; e < 4; e++) c[mt][nt][e] = 0.f;

    auto load_chunk = [&](int ch, int buf) {
        const int k0w = ch * 32;
        #pragma unroll
        for (int it = 0; it < 4; it++) {
            int row = lrow + it * 32;
            cp_async16(smem_u32(&Asb[buf * CHUNKW + row * SPAD + lc4]),
                       A + (size_t)(bm + row) * 256 + k0w + lc4);
            cp_async16(smem_u32(&Bsb[buf * CHUNKW + row * SPAD + lc4]),
                       BT + (size_t)(bn + row) * 256 + k0w + lc4);
        }
        CP_COMMIT();
    };

    load_chunk(0, 0);
    load_chunk(1, 1);
    #pragma unroll 1
    for (int ch = 0; ch < NCH; ch++) {
        if (ch + 1 < NCH) { CP_WAIT(1); } else { CP_WAIT(0); }
        __syncthreads();

        const uint32_t bufOff = (uint32_t)((ch % 3) * CHUNKW) << 2;
        #pragma unroll
        for (int s = 0; s < 4; s++) {       // 4 k16-steps (8 words each)
            const uint32_t kOff = (uint32_t)(s * 8) << 2;
            uint32_t af[4][4], bf[4][2];
            #pragma unroll
            for (int mt = 0; mt < 4; mt++)
                ldsm4(af[mt][0], af[mt][1], af[mt][2], af[mt][3],
                      aAddr0 + bufOff + ((uint32_t)(mt * 16 * SPAD) << 2) + kOff);
            #pragma unroll
            for (int nt2 = 0; nt2 < 2; nt2++)
                ldsm4(bf[nt2*2][0], bf[nt2*2][1], bf[nt2*2+1][0], bf[nt2*2+1][1],
                      bAddr0 + bufOff + ((uint32_t)(nt2 * 16 * SPAD) << 2) + kOff);
            #pragma unroll
            for (int mt = 0; mt < 4; mt++)
                #pragma unroll
                for (int nt = 0; nt < 4; nt++)
                    mma_f16(c[mt][nt], af[mt], bf[nt]);
        }
        if (ch + 2 < NCH) load_chunk(ch + 2, (ch + 2) % 3);
    }

    if (mode == 0) {
        // scatter q/k/v as packed half2
        const int nwbase = bn + warp_n * 32;
        const int s      = nwbase >> 9;
        const int head   = (nwbase & 511) >> 5;
        uint32_t* basep = (s == 0) ? g_q : ((s == 1) ? g_k : g_v);
        const float scl = (s == 0) ? QSCALE : 1.0f;
        #pragma unroll
        for (int mt = 0; mt < 4; mt++) {
            #pragma unroll
            for (int half = 0; half < 2; half++) {
                int m = bm + warp_m * 64 + mt * 16 + grp + half * 8;
                int b = m / 784, p = m % 784;
                int h = p / 28, w = p % 28;
                int win  = b * NWIN + (h / 7) * 4 + (w / 7);
                int lpos = (h % 7) * 7 + (w % 7);
                uint32_t* dst = basep + (((size_t)(win * NH + head)) * L + lpos) * (HD/2);
                #pragma unroll
                for (int nt = 0; nt < 4; nt++) {
                    int n = nwbase + nt * 8 + 2 * thr;
                    int d2 = (n & 31) >> 1;
                    dst[d2] = pack2((c[mt][nt][half * 2 + 0] + bias[n + 0]) * scl,
                                    (c[mt][nt][half * 2 + 1] + bias[n + 1]) * scl);
                }
            }
        }
    } else {
        #pragma unroll
        for (int mt = 0; mt < 4; mt++) {
            #pragma unroll
            for (int half = 0; half < 2; half++) {
                size_t m = bm + warp_m * 64 + mt * 16 + grp + half * 8;
                #pragma unroll
                for (int nt = 0; nt < 4; nt++) {
                    int n = bn + warp_n * 32 + nt * 8 + 2 * thr;
                    float2 o;
                    o.x = c[mt][nt][half * 2 + 0] + bias[n + 0];
                    o.y = c[mt][nt][half * 2 + 1] + bias[n + 1];
                    *(float2*)(outp + m * 512 + n) = o;
                }
            }
        }
    }
}

// ======================= windowed attention (fp16 + ldmatrix) ==============
// qs [64][20], ks [64][20] (rows 49..63 zero), sp [64][36] (alias),
// vt [32][36] (ki 49..63 zero). All row strides 16B-aligned, conflict-free.
__global__ __launch_bounds__(128) void attn_kernel()
{
    __shared__ uint32_t sbuf[2560 + 32*36];   // 14.8 KB
    uint32_t (*qs)[20] = (uint32_t(*)[20])sbuf;            // [64][20]
    uint32_t (*ks)[20] = (uint32_t(*)[20])(sbuf + 64*20);  // [64][20]
    uint32_t (*sp)[36] = (uint32_t(*)[36])sbuf;            // [64][36] alias
    uint32_t (*vt)[36] = (uint32_t(*)[36])(sbuf + 2560);   // [32][36]

    const int wh     = blockIdx.x;
    const int head   = wh & 15;
    const int window = wh >> 4;
    const int winImg = window & (NWIN - 1);
    const int tid    = threadIdx.x;
    const int wid    = tid >> 5, lane = tid & 31;
    const int grp    = lane >> 2, thr = lane & 3;
    const int quad   = lane >> 3, lrw = lane & 7;

    const uint32_t* qp = g_q + (size_t)wh * L * (HD/2);
    const uint32_t* kp = g_k + (size_t)wh * L * (HD/2);
    const uint32_t* vp = g_v + (size_t)wh * L * (HD/2);

    // ---- staging ----
    __half* vth = (__half*)vt;             // row stride 72 halves
    for (int f = tid; f < 49 * 16; f += 128) {
        int l = f >> 4, w = f & 15;
        qs[l][w] = qp[f];
        ks[l][w] = kp[f];
        uint32_t vw = vp[f];
        __half2 h = *(__half2*)&vw;
        vth[(2 * w) * 72 + l]     = __low2half(h);
        vth[(2 * w + 1) * 72 + l] = __high2half(h);
    }
    for (int i = tid; i < 15 * 20; i += 128) {         // zero ks pad rows 49..63
        ks[49 + i / 20][i % 20] = 0u;
    }
    for (int f = tid; f < 32 * 15; f += 128) {         // zero vt ki 49..63
        int d = f / 15, l = 49 + f % 15;
        vth[d * 72 + l] = __float2half(0.f);
    }
    __syncthreads();

    // ---- scores: S = Q @ K^T (16 rows x 56 cols per warp) ----
    const int base = wid * 16;
    const uint32_t smb = smem_u32(sbuf);
    const uint32_t qAddr0 = smb +
        (((base + (quad & 1) * 8 + lrw) * 20 + (quad >> 1) * 4) << 2);
    const uint32_t kAddr0 = smb + ((64 * 20) << 2) +
        ((((quad >> 1) * 8 + lrw) * 20 + (quad & 1) * 4) << 2);

    float c[7][4];
    #pragma unroll
    for (int nt = 0; nt < 7; nt++)
        #pragma unroll
        for (int e = 0; e < 4; e++) c[nt][e] = 0.f;

    {
        uint32_t bf[8][2];
        #pragma unroll
        for (int s = 0; s < 2; s++) {          // 2 k16-steps over HD=32
            const uint32_t kOff = (uint32_t)(s * 8) << 2;
            uint32_t af[4];
            ldsm4(af[0], af[1], af[2], af[3], qAddr0 + kOff);
            #pragma unroll
            for (int nt2 = 0; nt2 < 4; nt2++)
                ldsm4(bf[nt2*2][0], bf[nt2*2][1], bf[nt2*2+1][0], bf[nt2*2+1][1],
                      kAddr0 + ((uint32_t)(nt2 * 16 * 20) << 2) + kOff);
            #pragma unroll
            for (int nt = 0; nt < 7; nt++)
                mma_f16(c[nt], af, bf[nt]);
        }
    }

    // ---- softmax in regs; bias+mask from g_bm ----
    const float* bmp = g_bm + (size_t)(winImg * 16 + head) * 64 * 56;
    float vals[2][14], inv[2];
    #pragma unroll
    for (int h = 0; h < 2; h++) {
        int r = base + grp + 8 * h;
        const float* bmr = bmp + r * 56 + 2 * thr;
        #pragma unroll
        for (int nt = 0; nt < 7; nt++) {
            float2 bv = *(const float2*)(bmr + nt * 8);
            vals[h][nt * 2 + 0] = c[nt][2 * h + 0] + bv.x;
            vals[h][nt * 2 + 1] = c[nt][2 * h + 1] + bv.y;
        }
        float mx = -1e30f;
        #pragma unroll
        for (int i = 0; i < 14; i++) mx = fmaxf(mx, vals[h][i]);
        mx = fmaxf(mx, __shfl_xor_sync(0xffffffffu, mx, 1));
        mx = fmaxf(mx, __shfl_xor_sync(0xffffffffu, mx, 2));
        float sum = 0.f;
        #pragma unroll
        for (int i = 0; i < 14; i++) {
            vals[h][i] = __expf(vals[h][i] - mx);
            sum += vals[h][i];
        }
        sum += __shfl_xor_sync(0xffffffffu, sum, 1);
        sum += __shfl_xor_sync(0xffffffffu, sum, 2);
        inv[h] = __frcp_rn(sum);
    }
    __syncthreads();   // all warps done reading qs/ks before P aliases them

    // P -> sp halves (warp-local rows); zero pad words 28..31 of own rows
    for (int i = lane; i < 16 * 4; i += 32) {
        sp[base + (i >> 2)][28 + (i & 3)] = 0u;
    }
    #pragma unroll
    for (int h = 0; h < 2; h++) {
        int r = base + grp + 8 * h;
        if (r < 49) {
            #pragma unroll
            for (int nt = 0; nt < 7; nt++) {
                sp[r][nt * 4 + thr] = pack2(vals[h][nt * 2 + 0] * inv[h],
                                            vals[h][nt * 2 + 1] * inv[h]);
            }
        }
    }
    __syncwarp();

    // ---- out = P @ V (16 rows x 32 dims per warp) ----
    const uint32_t pAddr0 = smb +
        (((base + (quad & 1) * 8 + lrw) * 36 + (quad >> 1) * 4) << 2);
    const uint32_t vAddr0 = smb + (2560u << 2) +
        ((((quad >> 1) * 8 + lrw) * 36 + (quad & 1) * 4) << 2);

    float o[4][4];
    #pragma unroll
    for (int nt = 0; nt < 4; nt++)
        #pragma unroll
        for (int e = 0; e < 4; e++) o[nt][e] = 0.f;

    #pragma unroll
    for (int s = 0; s < 4; s++) {          // 4 k16-steps over 64 padded keys
        const uint32_t kOff = (uint32_t)(s * 8) << 2;
        uint32_t af[4], bf[4][2];
        ldsm4(af[0], af[1], af[2], af[3], pAddr0 + kOff);
        #pragma unroll
        for (int nt2 = 0; nt2 < 2; nt2++)
            ldsm4(bf[nt2*2][0], bf[nt2*2][1], bf[nt2*2+1][0], bf[nt2*2+1][1],
                  vAddr0 + ((uint32_t)(nt2 * 16 * 36) << 2) + kOff);
        #pragma unroll
        for (int nt = 0; nt < 4; nt++)
            mma_f16(o[nt], af, bf[nt]);
    }

    // ---- window-reverse scatter to token-major g_ao (packed half2) ----
    const int b  = window >> 4;
    const int wi = window & 15;
    #pragma unroll
    for (int h = 0; h < 2; h++) {
        int r = base + grp + 8 * h;
        if (r < 49) {
            int hh = (wi >> 2) * 7 + r / 7;
            int ww = (wi & 3) * 7 + r % 7;
            size_t tok = (size_t)b * 784 + hh * 28 + ww;
            uint32_t* dst = g_ao + tok * (C/2) + head * (HD/2);
            #pragma unroll
            for (int nt = 0; nt < 4; nt++) {
                int d = nt * 8 + 2 * thr;
                dst[d >> 1] = pack2(o[nt][2 * h + 0], o[nt][2 * h + 1]);
            }
        }
    }
}

// =========================== launch ========================================
extern "C" void kernel_launch(void* const* d_in, const int* in_sizes, int n_in,
                              void* d_out, int out_size)
{
    // Bind by descending size rank (order/unit invariant)
    int order[16];
    int m = n_in > 16 ? 16 : n_in;
    for (int i = 0; i < m; i++) order[i] = i;
    for (int a = 0; a < m; a++) {
        int best = a;
        for (int b2 = a + 1; b2 < m; b2++)
            if ((unsigned)in_sizes[order[b2]] > (unsigned)in_sizes[order[best]])
                best = b2;
        int t = order[a]; order[a] = order[best]; order[best] = t;
    }
    const float* x          = (const float*)d_in[order[0]];
    const float* w_qkv      = (const float*)d_in[order[1]];
    const float* w_proj     = (const float*)d_in[order[2]];
    const float* mask       = (const float*)d_in[order[3]];
    const float* bias_table = (const float*)d_in[order[4]];
    const int*   rel_index  = (const int*)  d_in[order[5]];
    const float* b_qkv      = (const float*)d_in[order[6]];
    const float* b_proj     = (const float*)d_in[order[7]];
    float* out = (float*)d_out;

    const int gemm_smem = 6 * CHUNKW * 4;   // 110592 B (3 stages x A+B)
    cudaFuncSetAttribute(gemm_mma_kernel,
                         cudaFuncAttributeMaxDynamicSharedMemorySize, gemm_smem);

    // 0) one-shot prep: x->fp16, weight transposes, bias/mask table
    cvt_x_kernel<<<50176, 256>>>(x);
    wT16_kernel<<<1536, 256>>>(w_qkv, 1536, 0);
    wT16_kernel<<<512, 256>>>(w_proj, 512, 1);
    bm_precompute_kernel<<<256, 256>>>(mask, bias_table, rel_index);

    // 1) QKV projection (fp16 tensor cores) + window scatter
    gemm_mma_kernel<<<dim3(12, 784), 256, gemm_smem>>>(b_qkv, nullptr, 0);

    // 2) per-(window, head) attention (fp16 tensor cores)
    attn_kernel<<<NWH, 128>>>();

    // 3) output projection (fp16 tensor cores)
    gemm_mma_kernel<<<dim3(4, 784), 256, gemm_smem>>>(b_proj, out, 1);
}

// round 16
// speedup vs baseline: 1.1958x; 1.1958x over previous
#include <cuda_runtime.h>
#include <cuda_fp16.h>
#include <cstdint>

// Problem constants
#define Bsz   128
#define Himg  28
#define Wimg  28
#define C     512
#define WS    7
#define NH    16
#define HD    32
#define NWIN  16
#define L     49
#define NTOK  (Bsz*Himg*Wimg)        // 100352
#define NWH   (Bsz*NWIN*NH)          // 32768
#define QSCALE 0.17677669529663687f

// ---------------- scratch (device globals; packed half2 words) -------------
__device__ uint32_t g_q [Bsz*NWIN*NH*L*HD/2];   // [wh][l][d/2]
__device__ uint32_t g_k [Bsz*NWIN*NH*L*HD/2];
__device__ uint32_t g_v [Bsz*NWIN*NH*L*HD/2];
__device__ uint32_t g_ao[(size_t)NTOK*C/2];     // attn out halves [tok][256]
__device__ uint32_t g_x16[(size_t)NTOK*C/2];    // x halves [tok][256]
__device__ uint32_t g_wqkvT16[1536*256];        // w_qkv^T halves [n][k/2]
__device__ uint32_t g_wprojT16[512*256];        // w_proj^T halves [n][k/2]
__device__ float    g_bm[256*64*56];            // bias+mask [winImg*16+head][64][56]

__device__ __forceinline__ uint32_t pack2(float a, float b) {
    __half2 h = __floats2half2_rn(a, b);
    return *(uint32_t*)&h;
}
__device__ __forceinline__ uint32_t smem_u32(const void* p) {
    uint32_t a;
    asm("{ .reg .u64 t; cvta.to.shared.u64 t, %1; cvt.u32.u64 %0, t; }" : "=r"(a) : "l"(p));
    return a;
}
__device__ __forceinline__ void cp_async16(uint32_t dst, const void* src) {
    asm volatile("cp.async.cg.shared.global [%0], [%1], 16;" :: "r"(dst), "l"(src) : "memory");
}
#define CP_COMMIT()  asm volatile("cp.async.commit_group;" ::: "memory")
#define CP_WAIT(n)   asm volatile("cp.async.wait_group %0;" :: "n"(n) : "memory")

// ldmatrix x4 (sm_75+, arch-agnostic)
__device__ __forceinline__ void ldsm4(uint32_t& r0, uint32_t& r1, uint32_t& r2,
                                      uint32_t& r3, uint32_t addr) {
    asm volatile("ldmatrix.sync.aligned.m8n8.x4.shared.b16 {%0,%1,%2,%3}, [%4];"
                 : "=r"(r0), "=r"(r1), "=r"(r2), "=r"(r3) : "r"(addr));
}

// m16n8k16 f16 mma, fp32 accumulate
__device__ __forceinline__ void mma_f16(float* c, const uint32_t* a, const uint32_t* b) {
    asm volatile(
        "mma.sync.aligned.m16n8k16.row.col.f32.f16.f16.f32 "
        "{%0,%1,%2,%3}, {%4,%5,%6,%7}, {%8,%9}, {%0,%1,%2,%3};\n"
        : "+f"(c[0]), "+f"(c[1]), "+f"(c[2]), "+f"(c[3])
        : "r"(a[0]), "r"(a[1]), "r"(a[2]), "r"(a[3]), "r"(b[0]), "r"(b[1]));
}

// ======================= x -> half2 convert (one-shot) =====================
__global__ __launch_bounds__(256) void cvt_x_kernel(const float* __restrict__ x)
{
    size_t i = (size_t)blockIdx.x * 256 + threadIdx.x;   // float4 index
    float4 v = *(const float4*)(x + i * 4);
    uint2 w;
    w.x = pack2(v.x, v.y);
    w.y = pack2(v.z, v.w);
    *(uint2*)(g_x16 + i * 2) = w;
}

// ======================= weight transpose + cvt (tiny) =====================
__global__ void wT16_kernel(const float* __restrict__ src, int NC, int mode)
{
    uint32_t* dst = mode ? g_wprojT16 : g_wqkvT16;
    int n  = blockIdx.x;
    int kw = threadIdx.x;     // 0..255
    float a = src[(size_t)(2 * kw) * NC + n];
    float b = src[(size_t)(2 * kw + 1) * NC + n];
    dst[(size_t)n * 256 + kw] = pack2(a, b);
}

// ======================= bias+mask precompute (tiny, once) =================
__global__ void bm_precompute_kernel(const float* __restrict__ mask,
                                     const float* __restrict__ bias_table,
                                     const int*   __restrict__ rel_index)
{
    const int pair = blockIdx.x;            // winImg*16 + head
    const int winImg = pair >> 4, head = pair & 15;
    float* dst = g_bm + (size_t)pair * 64 * 56;
    for (int i = threadIdx.x; i < 64 * 56; i += blockDim.x) {
        int r = i / 56, col = i - r * 56;
        float v;
        if (r < 49)
            v = (col < 49)
                ? bias_table[rel_index[r * 49 + col] * NH + head] + mask[winImg * (L*L) + r * 49 + col]
                : -1e30f;
        else
            v = 0.f;
        dst[i] = v;
    }
}

// ======================= fp16 mma GEMM (BM=128, BN=256, 512 thr) ===========
// Traffic-optimized: BN=256 halves A-operand rereads. 2-stage cp.async,
// BK=64 halves (32 words), ldmatrix fragments. 16 warps in 4x4 grid;
// warp tile 32 rows x 64 cols (mt=2, nt=8).
#define SPAD   36
#define AW     (128*SPAD)            // A words per stage
#define BW     (256*SPAD)            // B words per stage
#define NCH    8                     // 512 halves / 64

__global__ __launch_bounds__(512) void gemm_mma_kernel(
    const float* __restrict__ bias, float* __restrict__ outp, int mode)
{
    extern __shared__ uint32_t dsm[];
    uint32_t* Asb = dsm;                 // [2][128][SPAD]
    uint32_t* Bsb = dsm + 2 * AW;        // [2][256][SPAD]

    const int tid  = threadIdx.x;
    const int wid  = tid >> 5, lane = tid & 31;
    const int warp_m = wid & 3;          // 4 warps over M (32 rows each)
    const int warp_n = wid >> 2;         // 4 warps over N (64 cols each)
    const int bm = blockIdx.y * 128;
    const int bn = blockIdx.x * 256;
    const int grp = lane >> 2, thr = lane & 3;
    const int quad = lane >> 3, lrw = lane & 7;

    const uint32_t* A  = (mode == 0) ? g_x16 : g_ao;
    const uint32_t* BT = (mode == 0) ? g_wqkvT16 : g_wprojT16;

    const int lrow = tid >> 3;            // 0..63
    const int lc4  = (tid & 7) << 2;      // 0..28

    // per-lane ldmatrix base addresses
    const uint32_t smb = smem_u32(dsm);
    const uint32_t aAddr0 = smb +
        (((warp_m * 32 + (quad & 1) * 8 + lrw) * SPAD + (quad >> 1) * 4) << 2);
    const uint32_t bAddr0 = smb + ((2 * AW) << 2) +
        (((warp_n * 64 + (quad >> 1) * 8 + lrw) * SPAD + (quad & 1) * 4) << 2);

    float c[2][8][4];
    #pragma unroll
    for (int mt = 0; mt < 2; mt++)
        #pragma unroll
        for (int nt = 0; nt < 8; nt++)
            #pragma unroll
            for (int e = 0; e < 4; e++) c[mt][nt][e] = 0.f;

    auto load_chunk = [&](int ch, int buf) {
        const int k0w = ch * 32;
        #pragma unroll
        for (int it = 0; it < 2; it++) {
            int row = lrow + it * 64;
            cp_async16(smem_u32(&Asb[buf * AW + row * SPAD + lc4]),
                       A + (size_t)(bm + row) * 256 + k0w + lc4);
        }
        #pragma unroll
        for (int it = 0; it < 4; it++) {
            int row = lrow + it * 64;
            cp_async16(smem_u32(&Bsb[buf * BW + row * SPAD + lc4]),
                       BT + (size_t)(bn + row) * 256 + k0w + lc4);
        }
        CP_COMMIT();
    };

    load_chunk(0, 0);
    #pragma unroll 1
    for (int ch = 0; ch < NCH; ch++) {
        if (ch + 1 < NCH) {
            load_chunk(ch + 1, (ch + 1) & 1);
            CP_WAIT(1);
        } else {
            CP_WAIT(0);
        }
        __syncthreads();

        const uint32_t aOff = (uint32_t)((ch & 1) * AW) << 2;
        const uint32_t bOff = (uint32_t)((ch & 1) * BW) << 2;
        #pragma unroll
        for (int s = 0; s < 4; s++) {       // 4 k16-steps (8 words each)
            const uint32_t kOff = (uint32_t)(s * 8) << 2;
            uint32_t af[2][4], bf[8][2];
            #pragma unroll
            for (int mt = 0; mt < 2; mt++)
                ldsm4(af[mt][0], af[mt][1], af[mt][2], af[mt][3],
                      aAddr0 + aOff + ((uint32_t)(mt * 16 * SPAD) << 2) + kOff);
            #pragma unroll
            for (int nt2 = 0; nt2 < 4; nt2++)
                ldsm4(bf[nt2*2][0], bf[nt2*2][1], bf[nt2*2+1][0], bf[nt2*2+1][1],
                      bAddr0 + bOff + ((uint32_t)(nt2 * 16 * SPAD) << 2) + kOff);
            #pragma unroll
            for (int mt = 0; mt < 2; mt++)
                #pragma unroll
                for (int nt = 0; nt < 8; nt++)
                    mma_f16(c[mt][nt], af[mt], bf[nt]);
        }
        __syncthreads();
    }

    if (mode == 0) {
        // scatter q/k/v as packed half2; head/s per 8-col nt block
        #pragma unroll
        for (int mt = 0; mt < 2; mt++) {
            #pragma unroll
            for (int half = 0; half < 2; half++) {
                int m = bm + warp_m * 32 + mt * 16 + grp + half * 8;
                int b = m / 784, p = m % 784;
                int h = p / 28, w = p % 28;
                int win  = b * NWIN + (h / 7) * 4 + (w / 7);
                int lpos = (h % 7) * 7 + (w % 7);
                size_t rowoff = ((size_t)win * NH) * L * (HD/2) + (size_t)lpos * (HD/2);
                #pragma unroll
                for (int nt = 0; nt < 8; nt++) {
                    int n = bn + warp_n * 64 + nt * 8 + 2 * thr;
                    int s = n >> 9;
                    int head = (n & 511) >> 5;
                    uint32_t* basep = (s == 0) ? g_q : ((s == 1) ? g_k : g_v);
                    float scl = (s == 0) ? QSCALE : 1.0f;
                    uint32_t* dst = basep + rowoff + (size_t)head * L * (HD/2);
                    int d2 = (n & 31) >> 1;
                    dst[d2] = pack2((c[mt][nt][half * 2 + 0] + bias[n + 0]) * scl,
                                    (c[mt][nt][half * 2 + 1] + bias[n + 1]) * scl);
                }
            }
        }
    } else {
        #pragma unroll
        for (int mt = 0; mt < 2; mt++) {
            #pragma unroll
            for (int half = 0; half < 2; half++) {
                size_t m = bm + warp_m * 32 + mt * 16 + grp + half * 8;
                #pragma unroll
                for (int nt = 0; nt < 8; nt++) {
                    int n = bn + warp_n * 64 + nt * 8 + 2 * thr;
                    float2 o;
                    o.x = c[mt][nt][half * 2 + 0] + bias[n + 0];
                    o.y = c[mt][nt][half * 2 + 1] + bias[n + 1];
                    *(float2*)(outp + m * 512 + n) = o;
                }
            }
        }
    }
}

// ======================= windowed attention (fp16 + ldmatrix) ==============
// qs [64][20], ks [64][20] (rows 49..63 zero), sp [64][36] (alias),
// vt [32][36] (ki 49..63 zero). All row strides 16B-aligned, conflict-free.
__global__ __launch_bounds__(128) void attn_kernel()
{
    __shared__ uint32_t sbuf[2560 + 32*36];   // 14.8 KB
    uint32_t (*qs)[20] = (uint32_t(*)[20])sbuf;            // [64][20]
    uint32_t (*ks)[20] = (uint32_t(*)[20])(sbuf + 64*20);  // [64][20]
    uint32_t (*sp)[36] = (uint32_t(*)[36])sbuf;            // [64][36] alias
    uint32_t (*vt)[36] = (uint32_t(*)[36])(sbuf + 2560);   // [32][36]

    const int wh     = blockIdx.x;
    const int head   = wh & 15;
    const int window = wh >> 4;
    const int winImg = window & (NWIN - 1);
    const int tid    = threadIdx.x;
    const int wid    = tid >> 5, lane = tid & 31;
    const int grp    = lane >> 2, thr = lane & 3;
    const int quad   = lane >> 3, lrw = lane & 7;

    const uint32_t* qp = g_q + (size_t)wh * L * (HD/2);
    const uint32_t* kp = g_k + (size_t)wh * L * (HD/2);
    const uint32_t* vp = g_v + (size_t)wh * L * (HD/2);

    // ---- staging ----
    __half* vth = (__half*)vt;             // row stride 72 halves
    for (int f = tid; f < 49 * 16; f += 128) {
        int l = f >> 4, w = f & 15;
        qs[l][w] = qp[f];
        ks[l][w] = kp[f];
        uint32_t vw = vp[f];
        __half2 h = *(__half2*)&vw;
        vth[(2 * w) * 72 + l]     = __low2half(h);
        vth[(2 * w + 1) * 72 + l] = __high2half(h);
    }
    for (int i = tid; i < 15 * 20; i += 128) {         // zero ks pad rows 49..63
        ks[49 + i / 20][i % 20] = 0u;
    }
    for (int f = tid; f < 32 * 15; f += 128) {         // zero vt ki 49..63
        int d = f / 15, l = 49 + f % 15;
        vth[d * 72 + l] = __float2half(0.f);
    }
    __syncthreads();

    // ---- scores: S = Q @ K^T (16 rows x 56 cols per warp) ----
    const int base = wid * 16;
    const uint32_t smb = smem_u32(sbuf);
    const uint32_t qAddr0 = smb +
        (((base + (quad & 1) * 8 + lrw) * 20 + (quad >> 1) * 4) << 2);
    const uint32_t kAddr0 = smb + ((64 * 20) << 2) +
        ((((quad >> 1) * 8 + lrw) * 20 + (quad & 1) * 4) << 2);

    float c[7][4];
    #pragma unroll
    for (int nt = 0; nt < 7; nt++)
        #pragma unroll
        for (int e = 0; e < 4; e++) c[nt][e] = 0.f;

    {
        uint32_t bf[8][2];
        #pragma unroll
        for (int s = 0; s < 2; s++) {          // 2 k16-steps over HD=32
            const uint32_t kOff = (uint32_t)(s * 8) << 2;
            uint32_t af[4];
            ldsm4(af[0], af[1], af[2], af[3], qAddr0 + kOff);
            #pragma unroll
            for (int nt2 = 0; nt2 < 4; nt2++)
                ldsm4(bf[nt2*2][0], bf[nt2*2][1], bf[nt2*2+1][0], bf[nt2*2+1][1],
                      kAddr0 + ((uint32_t)(nt2 * 16 * 20) << 2) + kOff);
            #pragma unroll
            for (int nt = 0; nt < 7; nt++)
                mma_f16(c[nt], af, bf[nt]);
        }
    }

    // ---- softmax in regs; bias+mask from g_bm ----
    const float* bmp = g_bm + (size_t)(winImg * 16 + head) * 64 * 56;
    float vals[2][14], inv[2];
    #pragma unroll
    for (int h = 0; h < 2; h++) {
        int r = base + grp + 8 * h;
        const float* bmr = bmp + r * 56 + 2 * thr;
        #pragma unroll
        for (int nt = 0; nt < 7; nt++) {
            float2 bv = *(const float2*)(bmr + nt * 8);
            vals[h][nt * 2 + 0] = c[nt][2 * h + 0] + bv.x;
            vals[h][nt * 2 + 1] = c[nt][2 * h + 1] + bv.y;
        }
        float mx = -1e30f;
        #pragma unroll
        for (int i = 0; i < 14; i++) mx = fmaxf(mx, vals[h][i]);
        mx = fmaxf(mx, __shfl_xor_sync(0xffffffffu, mx, 1));
        mx = fmaxf(mx, __shfl_xor_sync(0xffffffffu, mx, 2));
        float sum = 0.f;
        #pragma unroll
        for (int i = 0; i < 14; i++) {
            vals[h][i] = __expf(vals[h][i] - mx);
            sum += vals[h][i];
        }
        sum += __shfl_xor_sync(0xffffffffu, sum, 1);
        sum += __shfl_xor_sync(0xffffffffu, sum, 2);
        inv[h] = __frcp_rn(sum);
    }
    __syncthreads();   // all warps done reading qs/ks before P aliases them

    // P -> sp halves (warp-local rows); zero pad words 28..31 of own rows
    for (int i = lane; i < 16 * 4; i += 32) {
        sp[base + (i >> 2)][28 + (i & 3)] = 0u;
    }
    #pragma unroll
    for (int h = 0; h < 2; h++) {
        int r = base + grp + 8 * h;
        if (r < 49) {
            #pragma unroll
            for (int nt = 0; nt < 7; nt++) {
                sp[r][nt * 4 + thr] = pack2(vals[h][nt * 2 + 0] * inv[h],
                                            vals[h][nt * 2 + 1] * inv[h]);
            }
        }
    }
    __syncwarp();

    // ---- out = P @ V (16 rows x 32 dims per warp) ----
    const uint32_t pAddr0 = smb +
        (((base + (quad & 1) * 8 + lrw) * 36 + (quad >> 1) * 4) << 2);
    const uint32_t vAddr0 = smb + (2560u << 2) +
        ((((quad >> 1) * 8 + lrw) * 36 + (quad & 1) * 4) << 2);

    float o[4][4];
    #pragma unroll
    for (int nt = 0; nt < 4; nt++)
        #pragma unroll
        for (int e = 0; e < 4; e++) o[nt][e] = 0.f;

    #pragma unroll
    for (int s = 0; s < 4; s++) {          // 4 k16-steps over 64 padded keys
        const uint32_t kOff = (uint32_t)(s * 8) << 2;
        uint32_t af[4], bf[4][2];
        ldsm4(af[0], af[1], af[2], af[3], pAddr0 + kOff);
        #pragma unroll
        for (int nt2 = 0; nt2 < 2; nt2++)
            ldsm4(bf[nt2*2][0], bf[nt2*2][1], bf[nt2*2+1][0], bf[nt2*2+1][1],
                  vAddr0 + ((uint32_t)(nt2 * 16 * 36) << 2) + kOff);
        #pragma unroll
        for (int nt = 0; nt < 4; nt++)
            mma_f16(o[nt], af, bf[nt]);
    }

    // ---- window-reverse scatter to token-major g_ao (packed half2) ----
    const int b  = window >> 4;
    const int wi = window & 15;
    #pragma unroll
    for (int h = 0; h < 2; h++) {
        int r = base + grp + 8 * h;
        if (r < 49) {
            int hh = (wi >> 2) * 7 + r / 7;
            int ww = (wi & 3) * 7 + r % 7;
            size_t tok = (size_t)b * 784 + hh * 28 + ww;
            uint32_t* dst = g_ao + tok * (C/2) + head * (HD/2);
            #pragma unroll
            for (int nt = 0; nt < 4; nt++) {
                int d = nt * 8 + 2 * thr;
                dst[d >> 1] = pack2(o[nt][2 * h + 0], o[nt][2 * h + 1]);
            }
        }
    }
}

// =========================== launch ========================================
extern "C" void kernel_launch(void* const* d_in, const int* in_sizes, int n_in,
                              void* d_out, int out_size)
{
    // Bind by descending size rank (order/unit invariant)
    int order[16];
    int m = n_in > 16 ? 16 : n_in;
    for (int i = 0; i < m; i++) order[i] = i;
    for (int a = 0; a < m; a++) {
        int best = a;
        for (int b2 = a + 1; b2 < m; b2++)
            if ((unsigned)in_sizes[order[b2]] > (unsigned)in_sizes[order[best]])
                best = b2;
        int t = order[a]; order[a] = order[best]; order[best] = t;
    }
    const float* x          = (const float*)d_in[order[0]];
    const float* w_qkv      = (const float*)d_in[order[1]];
    const float* w_proj     = (const float*)d_in[order[2]];
    const float* mask       = (const float*)d_in[order[3]];
    const float* bias_table = (const float*)d_in[order[4]];
    const int*   rel_index  = (const int*)  d_in[order[5]];
    const float* b_qkv      = (const float*)d_in[order[6]];
    const float* b_proj     = (const float*)d_in[order[7]];
    float* out = (float*)d_out;

    const int gemm_smem = 2 * (AW + BW) * 4;   // 110592 B (2 stages, A+B)
    cudaFuncSetAttribute(gemm_mma_kernel,
                         cudaFuncAttributeMaxDynamicSharedMemorySize, gemm_smem);

    // 0) one-shot prep: x->fp16, weight transposes, bias/mask table
    cvt_x_kernel<<<50176, 256>>>(x);
    wT16_kernel<<<1536, 256>>>(w_qkv, 1536, 0);
    wT16_kernel<<<512, 256>>>(w_proj, 512, 1);
    bm_precompute_kernel<<<256, 256>>>(mask, bias_table, rel_index);

    // 1) QKV projection (fp16 tensor cores, BN=256) + window scatter
    gemm_mma_kernel<<<dim3(6, 784), 512, gemm_smem>>>(b_qkv, nullptr, 0);

    // 2) per-(window, head) attention (fp16 tensor cores)
    attn_kernel<<<NWH, 128>>>();

    // 3) output projection (fp16 tensor cores, BN=256)
    gemm_mma_kernel<<<dim3(2, 784), 512, gemm_smem>>>(b_proj, out, 1);
}

// round 17
// speedup vs baseline: 1.4198x; 1.1873x over previous
#include <cuda_runtime.h>
#include <cuda_fp16.h>
#include <cstdint>

// Problem constants
#define Bsz   128
#define Himg  28
#define Wimg  28
#define C     512
#define WS    7
#define NH    16
#define HD    32
#define NWIN  16
#define L     49
#define NTOK  (Bsz*Himg*Wimg)        // 100352
#define NWH   (Bsz*NWIN*NH)          // 32768
#define QSCALE 0.17677669529663687f

// ---------------- scratch (device globals; packed half2 words) -------------
__device__ uint32_t g_q [Bsz*NWIN*NH*L*HD/2];   // [wh][l][d/2]
__device__ uint32_t g_k [Bsz*NWIN*NH*L*HD/2];
__device__ uint32_t g_v [Bsz*NWIN*NH*L*HD/2];
__device__ uint32_t g_ao[(size_t)NTOK*C/2];     // attn out halves [tok][256]
__device__ uint32_t g_x16[(size_t)NTOK*C/2];    // x halves [tok][256]
__device__ uint32_t g_wqkvT16[1536*256];        // w_qkv^T halves [n][k/2]
__device__ uint32_t g_wprojT16[512*256];        // w_proj^T halves [n][k/2]
__device__ uint32_t g_bm16[256*64*28];          // bias+mask half2 [pair][64][28]

__device__ __forceinline__ uint32_t pack2(float a, float b) {
    __half2 h = __floats2half2_rn(a, b);
    return *(uint32_t*)&h;
}
__device__ __forceinline__ uint32_t smem_u32(const void* p) {
    uint32_t a;
    asm("{ .reg .u64 t; cvta.to.shared.u64 t, %1; cvt.u32.u64 %0, t; }" : "=r"(a) : "l"(p));
    return a;
}
__device__ __forceinline__ void cp_async16(uint32_t dst, const void* src) {
    asm volatile("cp.async.cg.shared.global [%0], [%1], 16;" :: "r"(dst), "l"(src) : "memory");
}
#define CP_COMMIT()  asm volatile("cp.async.commit_group;" ::: "memory")
#define CP_WAIT(n)   asm volatile("cp.async.wait_group %0;" :: "n"(n) : "memory")

// ldmatrix x4 (sm_75+, arch-agnostic)
__device__ __forceinline__ void ldsm4(uint32_t& r0, uint32_t& r1, uint32_t& r2,
                                      uint32_t& r3, uint32_t addr) {
    asm volatile("ldmatrix.sync.aligned.m8n8.x4.shared.b16 {%0,%1,%2,%3}, [%4];"
                 : "=r"(r0), "=r"(r1), "=r"(r2), "=r"(r3) : "r"(addr));
}

// m16n8k16 f16 mma, fp32 accumulate
__device__ __forceinline__ void mma_f16(float* c, const uint32_t* a, const uint32_t* b) {
    asm volatile(
        "mma.sync.aligned.m16n8k16.row.col.f32.f16.f16.f32 "
        "{%0,%1,%2,%3}, {%4,%5,%6,%7}, {%8,%9}, {%0,%1,%2,%3};\n"
        : "+f"(c[0]), "+f"(c[1]), "+f"(c[2]), "+f"(c[3])
        : "r"(a[0]), "r"(a[1]), "r"(a[2]), "r"(a[3]), "r"(b[0]), "r"(b[1]));
}

// ======================= x -> half2 convert (one-shot) =====================
__global__ __launch_bounds__(256) void cvt_x_kernel(const float* __restrict__ x)
{
    size_t i = (size_t)blockIdx.x * 256 + threadIdx.x;   // float4 index
    float4 v = *(const float4*)(x + i * 4);
    uint2 w;
    w.x = pack2(v.x, v.y);
    w.y = pack2(v.z, v.w);
    *(uint2*)(g_x16 + i * 2) = w;
}

// ======================= weight transpose + cvt (tiny) =====================
__global__ void wT16_kernel(const float* __restrict__ src, int NC, int mode)
{
    uint32_t* dst = mode ? g_wprojT16 : g_wqkvT16;
    int n  = blockIdx.x;
    int kw = threadIdx.x;     // 0..255
    float a = src[(size_t)(2 * kw) * NC + n];
    float b = src[(size_t)(2 * kw + 1) * NC + n];
    dst[(size_t)n * 256 + kw] = pack2(a, b);
}

// ======================= bias+mask precompute (tiny, once) =================
// g_bm16[pair][r][w]: half2 of cols (2w, 2w+1). Pad cols 49..55 = -30000
// (exp(-30000-mx)=0; stays finite in fp16). Rows >= 49 -> 0.
__global__ void bm_precompute_kernel(const float* __restrict__ mask,
                                     const float* __restrict__ bias_table,
                                     const int*   __restrict__ rel_index)
{
    const int pair = blockIdx.x;            // winImg*16 + head
    const int winImg = pair >> 4, head = pair & 15;
    uint32_t* dst = g_bm16 + (size_t)pair * 64 * 28;
    for (int i = threadIdx.x; i < 64 * 28; i += blockDim.x) {
        int r = i / 28, w = i - r * 28;
        float v0 = 0.f, v1 = 0.f;
        if (r < 49) {
            int c0 = 2 * w, c1 = 2 * w + 1;
            v0 = (c0 < 49)
                ? bias_table[rel_index[r * 49 + c0] * NH + head] + mask[winImg * (L*L) + r * 49 + c0]
                : -30000.f;
            v1 = (c1 < 49)
                ? bias_table[rel_index[r * 49 + c1] * NH + head] + mask[winImg * (L*L) + r * 49 + c1]
                : -30000.f;
        }
        dst[i] = pack2(v0, v1);
    }
}

// ======================= fp16 mma GEMM (round-14 config) ===================
// BM=128, BN=128, 256 thr, 2-stage cp.async, BK=64 halves, ldmatrix.
#define SPAD   36
#define CHUNKW (128*SPAD)
#define NCH    8                     // 512 halves / 64

__global__ __launch_bounds__(256) void gemm_mma_kernel(
    const float* __restrict__ bias, float* __restrict__ outp, int mode)
{
    extern __shared__ uint32_t dsm[];
    uint32_t* Asb = dsm;                 // [2][128][SPAD]
    uint32_t* Bsb = dsm + 2 * CHUNKW;

    const int tid  = threadIdx.x;
    const int wid  = tid >> 5, lane = tid & 31;
    const int warp_m = wid & 1;
    const int warp_n = wid >> 1;
    const int bm = blockIdx.y * 128;
    const int bn = blockIdx.x * 128;
    const int grp = lane >> 2, thr = lane & 3;
    const int quad = lane >> 3, lrw = lane & 7;   // ldmatrix lane mapping

    const uint32_t* A  = (mode == 0) ? g_x16 : g_ao;
    const uint32_t* BT = (mode == 0) ? g_wqkvT16 : g_wprojT16;

    const int lrow = tid >> 3;            // staging row 0..31
    const int lc4  = (tid & 7) << 2;      // staging word 0..28

    // per-lane ldmatrix base addresses
    const uint32_t smb = smem_u32(dsm);
    const uint32_t aAddr0 = smb +
        (((warp_m * 64 + (quad & 1) * 8 + lrw) * SPAD + (quad >> 1) * 4) << 2);
    const uint32_t bAddr0 = smb + ((2 * CHUNKW) << 2) +
        (((warp_n * 32 + (quad >> 1) * 8 + lrw) * SPAD + (quad & 1) * 4) << 2);

    float c[4][4][4];
    #pragma unroll
    for (int mt = 0; mt < 4; mt++)
        #pragma unroll
        for (int nt = 0; nt < 4; nt++)
            #pragma unroll
            for (int e = 0; e < 4; e++) c[mt][nt][e] = 0.f;

    auto load_chunk = [&](int ch, int buf) {
        const int k0w = ch * 32;
        #pragma unroll
        for (int it = 0; it < 4; it++) {
            int row = lrow + it * 32;
            cp_async16(smem_u32(&Asb[buf * CHUNKW + row * SPAD + lc4]),
                       A + (size_t)(bm + row) * 256 + k0w + lc4);
            cp_async16(smem_u32(&Bsb[buf * CHUNKW + row * SPAD + lc4]),
                       BT + (size_t)(bn + row) * 256 + k0w + lc4);
        }
        CP_COMMIT();
    };

    load_chunk(0, 0);
    for (int ch = 0; ch < NCH; ch++) {
        if (ch + 1 < NCH) {
            load_chunk(ch + 1, (ch + 1) & 1);
            CP_WAIT(1);
        } else {
            CP_WAIT(0);
        }
        __syncthreads();

        const uint32_t bufOff = (uint32_t)((ch & 1) * CHUNKW) << 2;
        #pragma unroll
        for (int s = 0; s < 4; s++) {       // 4 k16-steps (8 words each)
            const uint32_t kOff = (uint32_t)(s * 8) << 2;
            uint32_t af[4][4], bf[4][2];
            #pragma unroll
            for (int mt = 0; mt < 4; mt++)
                ldsm4(af[mt][0], af[mt][1], af[mt][2], af[mt][3],
                      aAddr0 + bufOff + ((uint32_t)(mt * 16 * SPAD) << 2) + kOff);
            #pragma unroll
            for (int nt2 = 0; nt2 < 2; nt2++)
                ldsm4(bf[nt2*2][0], bf[nt2*2][1], bf[nt2*2+1][0], bf[nt2*2+1][1],
                      bAddr0 + bufOff + ((uint32_t)(nt2 * 16 * SPAD) << 2) + kOff);
            #pragma unroll
            for (int mt = 0; mt < 4; mt++)
                #pragma unroll
                for (int nt = 0; nt < 4; nt++)
                    mma_f16(c[mt][nt], af[mt], bf[nt]);
        }
        __syncthreads();
    }

    if (mode == 0) {
        // scatter q/k/v as packed half2
        const int nwbase = bn + warp_n * 32;
        const int s      = nwbase >> 9;
        const int head   = (nwbase & 511) >> 5;
        uint32_t* basep = (s == 0) ? g_q : ((s == 1) ? g_k : g_v);
        const float scl = (s == 0) ? QSCALE : 1.0f;
        #pragma unroll
        for (int mt = 0; mt < 4; mt++) {
            #pragma unroll
            for (int half = 0; half < 2; half++) {
                int m = bm + warp_m * 64 + mt * 16 + grp + half * 8;
                int b = m / 784, p = m % 784;
                int h = p / 28, w = p % 28;
                int win  = b * NWIN + (h / 7) * 4 + (w / 7);
                int lpos = (h % 7) * 7 + (w % 7);
                uint32_t* dst = basep + (((size_t)(win * NH + head)) * L + lpos) * (HD/2);
                #pragma unroll
                for (int nt = 0; nt < 4; nt++) {
                    int n = nwbase + nt * 8 + 2 * thr;
                    int d2 = (n & 31) >> 1;
                    dst[d2] = pack2((c[mt][nt][half * 2 + 0] + bias[n + 0]) * scl,
                                    (c[mt][nt][half * 2 + 1] + bias[n + 1]) * scl);
                }
            }
        }
    } else {
        #pragma unroll
        for (int mt = 0; mt < 4; mt++) {
            #pragma unroll
            for (int half = 0; half < 2; half++) {
                size_t m = bm + warp_m * 64 + mt * 16 + grp + half * 8;
                #pragma unroll
                for (int nt = 0; nt < 4; nt++) {
                    int n = bn + warp_n * 32 + nt * 8 + 2 * thr;
                    float2 o;
                    o.x = c[mt][nt][half * 2 + 0] + bias[n + 0];
                    o.y = c[mt][nt][half * 2 + 1] + bias[n + 1];
                    *(float2*)(outp + m * 512 + n) = o;
                }
            }
        }
    }
}

// ======================= windowed attention (fp16 + ldmatrix) ==============
// qs [64][20], ks [64][20] (rows 49..63 zero), sp [64][36] (alias),
// vt [32][36] (ki 49..63 zero). All row strides 16B-aligned, conflict-free.
__global__ __launch_bounds__(128) void attn_kernel()
{
    __shared__ uint32_t sbuf[2560 + 32*36];   // 14.8 KB
    uint32_t (*qs)[20] = (uint32_t(*)[20])sbuf;            // [64][20]
    uint32_t (*ks)[20] = (uint32_t(*)[20])(sbuf + 64*20);  // [64][20]
    uint32_t (*sp)[36] = (uint32_t(*)[36])sbuf;            // [64][36] alias
    uint32_t (*vt)[36] = (uint32_t(*)[36])(sbuf + 2560);   // [32][36]

    const int wh     = blockIdx.x;
    const int head   = wh & 15;
    const int window = wh >> 4;
    const int winImg = window & (NWIN - 1);
    const int tid    = threadIdx.x;
    const int wid    = tid >> 5, lane = tid & 31;
    const int grp    = lane >> 2, thr = lane & 3;
    const int quad   = lane >> 3, lrw = lane & 7;

    const uint32_t* qp = g_q + (size_t)wh * L * (HD/2);
    const uint32_t* kp = g_k + (size_t)wh * L * (HD/2);
    const uint32_t* vp = g_v + (size_t)wh * L * (HD/2);

    // ---- staging ----
    __half* vth = (__half*)vt;             // row stride 72 halves
    for (int f = tid; f < 49 * 16; f += 128) {
        int l = f >> 4, w = f & 15;
        qs[l][w] = qp[f];
        ks[l][w] = kp[f];
        uint32_t vw = vp[f];
        __half2 h = *(__half2*)&vw;
        vth[(2 * w) * 72 + l]     = __low2half(h);
        vth[(2 * w + 1) * 72 + l] = __high2half(h);
    }
    for (int i = tid; i < 15 * 20; i += 128) {         // zero ks pad rows 49..63
        ks[49 + i / 20][i % 20] = 0u;
    }
    for (int f = tid; f < 32 * 15; f += 128) {         // zero vt ki 49..63
        int d = f / 15, l = 49 + f % 15;
        vth[d * 72 + l] = __float2half(0.f);
    }
    __syncthreads();

    // ---- scores: S = Q @ K^T (16 rows x 56 cols per warp) ----
    const int base = wid * 16;
    const uint32_t smb = smem_u32(sbuf);
    const uint32_t qAddr0 = smb +
        (((base + (quad & 1) * 8 + lrw) * 20 + (quad >> 1) * 4) << 2);
    const uint32_t kAddr0 = smb + ((64 * 20) << 2) +
        ((((quad >> 1) * 8 + lrw) * 20 + (quad & 1) * 4) << 2);

    float c[7][4];
    #pragma unroll
    for (int nt = 0; nt < 7; nt++)
        #pragma unroll
        for (int e = 0; e < 4; e++) c[nt][e] = 0.f;

    {
        uint32_t bf[8][2];
        #pragma unroll
        for (int s = 0; s < 2; s++) {          // 2 k16-steps over HD=32
            const uint32_t kOff = (uint32_t)(s * 8) << 2;
            uint32_t af[4];
            ldsm4(af[0], af[1], af[2], af[3], qAddr0 + kOff);
            #pragma unroll
            for (int nt2 = 0; nt2 < 4; nt2++)
                ldsm4(bf[nt2*2][0], bf[nt2*2][1], bf[nt2*2+1][0], bf[nt2*2+1][1],
                      kAddr0 + ((uint32_t)(nt2 * 16 * 20) << 2) + kOff);
            #pragma unroll
            for (int nt = 0; nt < 7; nt++)
                mma_f16(c[nt], af, bf[nt]);
        }
    }

    // ---- softmax in regs; bias+mask from g_bm16 (half2) ----
    const uint32_t* bmp = g_bm16 + (size_t)(winImg * 16 + head) * 64 * 28;
    float vals[2][14], inv[2];
    #pragma unroll
    for (int h = 0; h < 2; h++) {
        int r = base + grp + 8 * h;
        const uint32_t* bmr = bmp + r * 28 + thr;   // word = cols (2thr, 2thr+1)
        #pragma unroll
        for (int nt = 0; nt < 7; nt++) {
            uint32_t bw = bmr[nt * 4];
            float2 bv = __half22float2(*(__half2*)&bw);
            vals[h][nt * 2 + 0] = c[nt][2 * h + 0] + bv.x;
            vals[h][nt * 2 + 1] = c[nt][2 * h + 1] + bv.y;
        }
        float mx = -1e30f;
        #pragma unroll
        for (int i = 0; i < 14; i++) mx = fmaxf(mx, vals[h][i]);
        mx = fmaxf(mx, __shfl_xor_sync(0xffffffffu, mx, 1));
        mx = fmaxf(mx, __shfl_xor_sync(0xffffffffu, mx, 2));
        float sum = 0.f;
        #pragma unroll
        for (int i = 0; i < 14; i++) {
            vals[h][i] = __expf(vals[h][i] - mx);
            sum += vals[h][i];
        }
        sum += __shfl_xor_sync(0xffffffffu, sum, 1);
        sum += __shfl_xor_sync(0xffffffffu, sum, 2);
        inv[h] = __frcp_rn(sum);
    }
    __syncthreads();   // all warps done reading qs/ks before P aliases them

    // P -> sp halves (warp-local rows); zero pad words 28..31 of own rows
    for (int i = lane; i < 16 * 4; i += 32) {
        sp[base + (i >> 2)][28 + (i & 3)] = 0u;
    }
    #pragma unroll
    for (int h = 0; h < 2; h++) {
        int r = base + grp + 8 * h;
        if (r < 49) {
            #pragma unroll
            for (int nt = 0; nt < 7; nt++) {
                sp[r][nt * 4 + thr] = pack2(vals[h][nt * 2 + 0] * inv[h],
                                            vals[h][nt * 2 + 1] * inv[h]);
            }
        }
    }
    __syncwarp();

    // ---- out = P @ V (16 rows x 32 dims per warp) ----
    const uint32_t pAddr0 = smb +
        (((base + (quad & 1) * 8 + lrw) * 36 + (quad >> 1) * 4) << 2);
    const uint32_t vAddr0 = smb + (2560u << 2) +
        ((((quad >> 1) * 8 + lrw) * 36 + (quad & 1) * 4) << 2);

    float o[4][4];
    #pragma unroll
    for (int nt = 0; nt < 4; nt++)
        #pragma unroll
        for (int e = 0; e < 4; e++) o[nt][e] = 0.f;

    #pragma unroll
    for (int s = 0; s < 4; s++) {          // 4 k16-steps over 64 padded keys
        const uint32_t kOff = (uint32_t)(s * 8) << 2;
        uint32_t af[4], bf[4][2];
        ldsm4(af[0], af[1], af[2], af[3], pAddr0 + kOff);
        #pragma unroll
        for (int nt2 = 0; nt2 < 2; nt2++)
            ldsm4(bf[nt2*2][0], bf[nt2*2][1], bf[nt2*2+1][0], bf[nt2*2+1][1],
                  vAddr0 + ((uint32_t)(nt2 * 16 * 36) << 2) + kOff);
        #pragma unroll
        for (int nt = 0; nt < 4; nt++)
            mma_f16(o[nt], af, bf[nt]);
    }

    // ---- window-reverse scatter to token-major g_ao (packed half2) ----
    const int b  = window >> 4;
    const int wi = window & 15;
    #pragma unroll
    for (int h = 0; h < 2; h++) {
        int r = base + grp + 8 * h;
        if (r < 49) {
            int hh = (wi >> 2) * 7 + r / 7;
            int ww = (wi & 3) * 7 + r % 7;
            size_t tok = (size_t)b * 784 + hh * 28 + ww;
            uint32_t* dst = g_ao + tok * (C/2) + head * (HD/2);
            #pragma unroll
            for (int nt = 0; nt < 4; nt++) {
                int d = nt * 8 + 2 * thr;
                dst[d >> 1] = pack2(o[nt][2 * h + 0], o[nt][2 * h + 1]);
            }
        }
    }
}

// =========================== launch ========================================
extern "C" void kernel_launch(void* const* d_in, const int* in_sizes, int n_in,
                              void* d_out, int out_size)
{
    // Bind by descending size rank (order/unit invariant)
    int order[16];
    int m = n_in > 16 ? 16 : n_in;
    for (int i = 0; i < m; i++) order[i] = i;
    for (int a = 0; a < m; a++) {
        int best = a;
        for (int b2 = a + 1; b2 < m; b2++)
            if ((unsigned)in_sizes[order[b2]] > (unsigned)in_sizes[order[best]])
                best = b2;
        int t = order[a]; order[a] = order[best]; order[best] = t;
    }
    const float* x          = (const float*)d_in[order[0]];
    const float* w_qkv      = (const float*)d_in[order[1]];
    const float* w_proj     = (const float*)d_in[order[2]];
    const float* mask       = (const float*)d_in[order[3]];
    const float* bias_table = (const float*)d_in[order[4]];
    const int*   rel_index  = (const int*)  d_in[order[5]];
    const float* b_qkv      = (const float*)d_in[order[6]];
    const float* b_proj     = (const float*)d_in[order[7]];
    float* out = (float*)d_out;

    const int gemm_smem = 4 * CHUNKW * 4;   // 73728 B (round-14 config)
    cudaFuncSetAttribute(gemm_mma_kernel,
                         cudaFuncAttributeMaxDynamicSharedMemorySize, gemm_smem);

    // 0) one-shot prep: x->fp16, weight transposes, bias/mask table
    cvt_x_kernel<<<50176, 256>>>(x);
    wT16_kernel<<<1536, 256>>>(w_qkv, 1536, 0);
    wT16_kernel<<<512, 256>>>(w_proj, 512, 1);
    bm_precompute_kernel<<<256, 256>>>(mask, bias_table, rel_index);

    // 1) QKV projection (fp16 tensor cores) + window scatter
    gemm_mma_kernel<<<dim3(12, 784), 256, gemm_smem>>>(b_qkv, nullptr, 0);

    // 2) per-(window, head) attention (fp16 tensor cores)
    attn_kernel<<<NWH, 128>>>();

    // 3) output projection (fp16 tensor cores)
    gemm_mma_kernel<<<dim3(4, 784), 256, gemm_smem>>>(b_proj, out, 1);
}